// round 11
// baseline (speedup 1.0000x reference)
#include <cuda_runtime.h>
#include <cstdint>

// out_i = sign(x) * u_i / ||u||, u = W[0,1:4]; 0 when x == 0.
// R2's winning shape (1024 CTAs x 256 thr, front-batched loads, block-
// contiguous chunks, single wave) upgraded to plain 256-bit LDG/STG:
// half the LSU issue slots, no cache hints (hints measured -0.6us).

#define HWPIX (512 * 512)            // 2^18 elements per plane
#define NBATCH 16
#define ITERS 2                      // 8 floats per iter per thread
#define THREADS 256
#define BLOCK_ELEMS (THREADS * ITERS * 8)   // 4096 elems per block

__device__ __forceinline__ void ld8(const float* p, float f[8]) {
    unsigned long long a, b, c, d;
    asm volatile("ld.global.nc.v4.b64 {%0,%1,%2,%3}, [%4];"
                 : "=l"(a), "=l"(b), "=l"(c), "=l"(d) : "l"(p));
    f[0] = __uint_as_float((unsigned)a); f[1] = __uint_as_float((unsigned)(a >> 32));
    f[2] = __uint_as_float((unsigned)b); f[3] = __uint_as_float((unsigned)(b >> 32));
    f[4] = __uint_as_float((unsigned)c); f[5] = __uint_as_float((unsigned)(c >> 32));
    f[6] = __uint_as_float((unsigned)d); f[7] = __uint_as_float((unsigned)(d >> 32));
}

__device__ __forceinline__ unsigned long long pack2(float lo, float hi) {
    return (unsigned long long)__float_as_uint(lo)
         | ((unsigned long long)__float_as_uint(hi) << 32);
}

__device__ __forceinline__ void st8(float* p, const float f[8]) {
    unsigned long long a = pack2(f[0], f[1]);
    unsigned long long b = pack2(f[2], f[3]);
    unsigned long long c = pack2(f[4], f[5]);
    unsigned long long d = pack2(f[6], f[7]);
    asm volatile("st.global.v4.b64 [%0], {%1,%2,%3,%4};"
                 :: "l"(p), "l"(a), "l"(b), "l"(c), "l"(d) : "memory");
}

__global__ __launch_bounds__(THREADS) void scene_normal_kernel(
    const float* __restrict__ depth,    // [16*512*512]
    const float* __restrict__ Wm,       // [8,8] row-major
    float* __restrict__ out)            // [16,3,512,512] flat
{
    const float u1 = Wm[1];
    const float u2 = Wm[2];
    const float u3 = Wm[3];
    const float r  = rsqrtf(u1 * u1 + u2 * u2 + u3 * u3);
    const float c1 = u1 * r, c2 = u2 * r, c3 = u3 * r;

    const int n0   = blockIdx.x * BLOCK_ELEMS;   // block-contiguous chunk
    const int b    = n0 >> 18;                   // HWPIX | BLOCK_ELEMS*64
    const int rem0 = n0 & (HWPIX - 1);

    const float* p = depth + n0 + threadIdx.x * 8;
    float* basep   = out + (size_t)b * 3 * HWPIX + rem0 + threadIdx.x * 8;

    // Front-batch both 256-bit loads (R2's winning pattern), then store.
    float x0[8], x1[8];
    ld8(p, x0);
    ld8(p + THREADS * 8, x1);

    float s0[8], s1[8], o[8];
#pragma unroll
    for (int j = 0; j < 8; j++)
        s0[j] = (x0[j] > 0.f) ? 1.f : ((x0[j] < 0.f) ? -1.f : 0.f);
#pragma unroll
    for (int j = 0; j < 8; j++)
        s1[j] = (x1[j] > 0.f) ? 1.f : ((x1[j] < 0.f) ? -1.f : 0.f);

#pragma unroll
    for (int j = 0; j < 8; j++) o[j] = s0[j] * c1;
    st8(basep, o);
#pragma unroll
    for (int j = 0; j < 8; j++) o[j] = s0[j] * c2;
    st8(basep + HWPIX, o);
#pragma unroll
    for (int j = 0; j < 8; j++) o[j] = s0[j] * c3;
    st8(basep + 2 * HWPIX, o);

    float* basep1 = basep + THREADS * 8;
#pragma unroll
    for (int j = 0; j < 8; j++) o[j] = s1[j] * c1;
    st8(basep1, o);
#pragma unroll
    for (int j = 0; j < 8; j++) o[j] = s1[j] * c2;
    st8(basep1 + HWPIX, o);
#pragma unroll
    for (int j = 0; j < 8; j++) o[j] = s1[j] * c3;
    st8(basep1 + 2 * HWPIX, o);
}

extern "C" void kernel_launch(void* const* d_in, const int* in_sizes, int n_in,
                              void* d_out, int out_size)
{
    const float* depth = (const float*)d_in[0];
    const float* Wm    = (const float*)d_in[1];
    float* out         = (float*)d_out;

    const int n_elems = NBATCH * HWPIX;          // 4,194,304
    const int blocks  = n_elems / BLOCK_ELEMS;   // 1024 (single wave)

    scene_normal_kernel<<<blocks, THREADS>>>(depth, Wm, out);
}

// round 12
// speedup vs baseline: 1.0201x; 1.0201x over previous
#include <cuda_runtime.h>

// FINAL: out_i = sign(x) * u_i / ||u||, u = W[0,1:4]; 0 when x == 0.
// (The reference's spectral norm, Euler scan, and normalization all cancel
//  algebraically; only the sign of depth and the direction of W[0,1:4]
//  survive.) Empirically best shape over 11 rounds: single wave, 1024 CTAs
//  x 256 thr, block-contiguous chunks, front-batched float4 loads, plain
//  STG.128. Steady state is bound by the mandatory 64MB LTS traffic.

#define HWPIX (512 * 512)            // 2^18 elements per plane
#define NBATCH 16
#define F4_PER_THREAD 4
#define THREADS 256
#define BLOCK_ELEMS (THREADS * F4_PER_THREAD * 4)   // 4096 elems per block

__global__ __launch_bounds__(THREADS) void scene_normal_kernel(
    const float4* __restrict__ depth4,   // [16*512*512/4]
    const float*  __restrict__ Wm,       // [8,8] row-major
    float* __restrict__ out)             // [16,3,512,512] flat
{
    const float u1 = Wm[1];
    const float u2 = Wm[2];
    const float u3 = Wm[3];
    const float r  = rsqrtf(u1 * u1 + u2 * u2 + u3 * u3);
    const float c1 = u1 * r, c2 = u2 * r, c3 = u3 * r;

    // Block-contiguous chunk; one wave; all accesses warp-coalesced.
    const int n0   = blockIdx.x * BLOCK_ELEMS;        // first element of block
    const int b    = n0 >> 18;                        // HWPIX | BLOCK_ELEMS*64
    const int rem0 = n0 & (HWPIX - 1);

    const float4* in4 = depth4 + (n0 >> 2) + threadIdx.x;
    float4* o1 = reinterpret_cast<float4*>(out + (size_t)b * 3 * HWPIX + rem0) + threadIdx.x;
    float4* o2 = reinterpret_cast<float4*>(out + (size_t)b * 3 * HWPIX + HWPIX + rem0) + threadIdx.x;
    float4* o3 = reinterpret_cast<float4*>(out + (size_t)b * 3 * HWPIX + 2 * HWPIX + rem0) + threadIdx.x;

    // Front-batch all loads: MLP per thread = 4
    float4 x[F4_PER_THREAD];
#pragma unroll
    for (int i = 0; i < F4_PER_THREAD; i++)
        x[i] = in4[i * THREADS];

#pragma unroll
    for (int i = 0; i < F4_PER_THREAD; i++) {
        const float s0 = (x[i].x > 0.f) ? 1.f : ((x[i].x < 0.f) ? -1.f : 0.f);
        const float s1 = (x[i].y > 0.f) ? 1.f : ((x[i].y < 0.f) ? -1.f : 0.f);
        const float s2 = (x[i].z > 0.f) ? 1.f : ((x[i].z < 0.f) ? -1.f : 0.f);
        const float s3 = (x[i].w > 0.f) ? 1.f : ((x[i].w < 0.f) ? -1.f : 0.f);

        float4 o;
        o.x = s0 * c1; o.y = s1 * c1; o.z = s2 * c1; o.w = s3 * c1;
        o1[i * THREADS] = o;
        o.x = s0 * c2; o.y = s1 * c2; o.z = s2 * c2; o.w = s3 * c2;
        o2[i * THREADS] = o;
        o.x = s0 * c3; o.y = s1 * c3; o.z = s2 * c3; o.w = s3 * c3;
        o3[i * THREADS] = o;
    }
}

extern "C" void kernel_launch(void* const* d_in, const int* in_sizes, int n_in,
                              void* d_out, int out_size)
{
    const float4* depth4 = (const float4*)d_in[0];
    const float*  Wm     = (const float*)d_in[1];
    float* out           = (float*)d_out;

    const int n_elems = NBATCH * HWPIX;             // 4,194,304
    const int blocks  = n_elems / BLOCK_ELEMS;      // 1024 (single wave)

    scene_normal_kernel<<<blocks, THREADS>>>(depth4, Wm, out);
}